// round 10
// baseline (speedup 1.0000x reference)
#include <cuda_runtime.h>
#include <float.h>

// Problem constants: B=32, C=64, H=W=64, code_size=512, BETA=0.25
#define Bn   32
#define Cn   64
#define HWn  4096
#define CBn  512
#define ST_ELEMS  (Bn * Cn * HWn)   // 8388608
#define IDX_ELEMS (Bn * HWn)        // 131072
#define GRID      128               // 1024 warps: 4096 tiles / 1024 = exactly 4 each
#define NTHREADS  256
#define NWARPS    8
// smem: codebook 512*64 floats + cnorm 512 floats
#define SMEMSZ (CBn * Cn * 4 + CBn * 4)

typedef unsigned long long ull;

__device__ float g_blocksums[GRID];
__device__ unsigned int g_done_ctr = 0;

static __device__ __forceinline__ void fma2(ull &acc, ull a, ull b) {
    asm("fma.rn.f32x2 %0, %1, %2, %0;" : "+l"(acc) : "l"(a), "l"(b));
}
static __device__ __forceinline__ ull pack2(float lo, float hi) {
    ull r; asm("mov.b64 %0, {%1, %2};" : "=l"(r) : "f"(lo), "f"(hi)); return r;
}
static __device__ __forceinline__ float2 unpack2(ull v) {
    float2 r; asm("mov.b64 {%0, %1}, %2;" : "=f"(r.x), "=f"(r.y) : "l"(v)); return r;
}

// Persistent kernel: grid=128, 256 threads (8 warps). Global warp id
// w = bid*8 + wid owns row-tiles 4w..4w+3: same 32-wide hw block
// (hwbase = (w>>3)*32), batches b = (4w&31)..(4w&31)+3.
// Pass A: 3 rows/thread (b0,b1,b2) — 6 FMA chains, LDS amortized 3x.
// Pass B: 1 row/thread (b3).
// Row n = hw*B + b of the (N, C) matrix = inputs[b, :, hw].
__global__ void __launch_bounds__(NTHREADS, 1) vq_kernel(
    const float* __restrict__ inp,   // (B, C, H, W)
    const float* __restrict__ cb,    // (512, 64)
    float* __restrict__ out,
    long long out_size)
{
    extern __shared__ float smem[];
    float* scb = smem;              // codebook, row-major 512x64
    float* scn = smem + CBn * Cn;   // per-code squared norms

    const int tid  = threadIdx.x;
    const int wid  = tid >> 5;
    const int lane = tid & 31;

    // Cooperative codebook load into smem (float4).
    for (int i = tid; i < CBn * Cn / 4; i += NTHREADS)
        ((float4*)scb)[i] = ((const float4*)cb)[i];

    // Per-code squared norms (4-lane accumulate + pairwise combine) —
    // identical arithmetic to the passing kernels.
    for (int j = tid; j < CBn; j += NTHREADS) {
        const float4* r = (const float4*)(cb + j * Cn);
        float sa = 0.f, sb = 0.f, sc = 0.f, sd = 0.f;
        #pragma unroll
        for (int i = 0; i < 16; i++) {
            float4 v = r[i];
            sa = fmaf(v.x, v.x, sa);
            sb = fmaf(v.y, v.y, sb);
            sc = fmaf(v.z, v.z, sc);
            sd = fmaf(v.w, v.w, sd);
        }
        scn[j] = (sa + sb) + (sc + sd);
    }
    __syncthreads();

    float lsum = 0.f;

    const int w      = blockIdx.x * NWARPS + wid;   // 0..1023
    const int b0     = (4 * w) & 31;
    const int hw     = ((w >> 3) << 5) + lane;
    const float* __restrict__ base = inp + hw;

    // ---------------- Pass A: rows (b0, b0+1, b0+2) ----------------
    {
        const float* rp0 = base + (size_t)(b0 + 0) * Cn * HWn;
        const float* rp1 = base + (size_t)(b0 + 1) * Cn * HWn;
        const float* rp2 = base + (size_t)(b0 + 2) * Cn * HWn;

        ull x0[32], x1[32], x2[32];
        #pragma unroll
        for (int i = 0; i < 32; i++) {
            x0[i] = pack2(rp0[(size_t)(2 * i) * HWn], rp0[(size_t)(2 * i + 1) * HWn]);
            x1[i] = pack2(rp1[(size_t)(2 * i) * HWn], rp1[(size_t)(2 * i + 1) * HWn]);
            x2[i] = pack2(rp2[(size_t)(2 * i) * HWn], rp2[(size_t)(2 * i + 1) * HWn]);
        }

        // Row squared norms — same accumulator split as the passing kernels.
        ull n0a = 0, n0b = 0, n1a = 0, n1b = 0, n2a = 0, n2b = 0;
        #pragma unroll
        for (int i = 0; i < 16; i++) {
            fma2(n0a, x0[2 * i],     x0[2 * i]);
            fma2(n0b, x0[2 * i + 1], x0[2 * i + 1]);
            fma2(n1a, x1[2 * i],     x1[2 * i]);
            fma2(n1b, x1[2 * i + 1], x1[2 * i + 1]);
            fma2(n2a, x2[2 * i],     x2[2 * i]);
            fma2(n2b, x2[2 * i + 1], x2[2 * i + 1]);
        }
        float2 t0 = unpack2(n0a), t1 = unpack2(n0b);
        const float xx0 = (t0.x + t0.y) + (t1.x + t1.y);
        float2 t2 = unpack2(n1a), t3 = unpack2(n1b);
        const float xx1 = (t2.x + t2.y) + (t3.x + t3.y);
        float2 t4 = unpack2(n2a), t5 = unpack2(n2b);
        const float xx2 = (t4.x + t4.y) + (t5.x + t5.y);

        float best0 = FLT_MAX, best1 = FLT_MAX, best2 = FLT_MAX;
        int bj0 = 0, bj1 = 0, bj2 = 0;

        #pragma unroll 1
        for (int j = 0; j < CBn; j++) {
            const ull* __restrict__ crow = (const ull*)(scb + j * Cn);
            ull a0 = 0, a1 = 0, c0 = 0, c1 = 0, e0 = 0, e1 = 0;
            #pragma unroll
            for (int i = 0; i < 16; i++) {
                ull ccx = crow[2 * i];
                ull ccy = crow[2 * i + 1];
                fma2(a0, x0[2 * i],     ccx);
                fma2(a1, x0[2 * i + 1], ccy);
                fma2(c0, x1[2 * i],     ccx);
                fma2(c1, x1[2 * i + 1], ccy);
                fma2(e0, x2[2 * i],     ccx);
                fma2(e1, x2[2 * i + 1], ccy);
            }
            float2 pa = unpack2(a0), pb = unpack2(a1);
            float dot0 = (pa.x + pa.y) + (pb.x + pb.y);
            float2 qa = unpack2(c0), qb = unpack2(c1);
            float dot1 = (qa.x + qa.y) + (qb.x + qb.y);
            float2 ra = unpack2(e0), rb = unpack2(e1);
            float dot2 = (ra.x + ra.y) + (rb.x + rb.y);

            float cn = scn[j];
            float d0 = (xx0 - 2.0f * dot0) + cn;
            float d1 = (xx1 - 2.0f * dot1) + cn;
            float d2 = (xx2 - 2.0f * dot2) + cn;
            if (d0 < best0) { best0 = d0; bj0 = j; }
            if (d1 < best1) { best1 = d1; bj1 = j; }
            if (d2 < best2) { best2 = d2; bj2 = j; }
        }

        // Epilogue: gather, write st + indices, loss partials.
        float* st0 = out + (size_t)(b0 + 0) * Cn * HWn + hw;
        float* st1 = out + (size_t)(b0 + 1) * Cn * HWn + hw;
        float* st2 = out + (size_t)(b0 + 2) * Cn * HWn + hw;
        const float4* c0r = (const float4*)(cb + bj0 * Cn);
        const float4* c1r = (const float4*)(cb + bj1 * Cn);
        const float4* c2r = (const float4*)(cb + bj2 * Cn);
        #pragma unroll
        for (int i = 0; i < 16; i++) {
            float4 v0 = c0r[i], v1 = c1r[i], v2 = c2r[i];
            float2 xa0 = unpack2(x0[2 * i]), xb0 = unpack2(x0[2 * i + 1]);
            float2 xa1 = unpack2(x1[2 * i]), xb1 = unpack2(x1[2 * i + 1]);
            float2 xa2 = unpack2(x2[2 * i]), xb2 = unpack2(x2[2 * i + 1]);

            st0[(size_t)(4 * i + 0) * HWn] = v0.x;
            st0[(size_t)(4 * i + 1) * HWn] = v0.y;
            st0[(size_t)(4 * i + 2) * HWn] = v0.z;
            st0[(size_t)(4 * i + 3) * HWn] = v0.w;
            st1[(size_t)(4 * i + 0) * HWn] = v1.x;
            st1[(size_t)(4 * i + 1) * HWn] = v1.y;
            st1[(size_t)(4 * i + 2) * HWn] = v1.z;
            st1[(size_t)(4 * i + 3) * HWn] = v1.w;
            st2[(size_t)(4 * i + 0) * HWn] = v2.x;
            st2[(size_t)(4 * i + 1) * HWn] = v2.y;
            st2[(size_t)(4 * i + 2) * HWn] = v2.z;
            st2[(size_t)(4 * i + 3) * HWn] = v2.w;

            float e;
            e = v0.x - xa0.x; lsum = fmaf(e, e, lsum);
            e = v0.y - xa0.y; lsum = fmaf(e, e, lsum);
            e = v0.z - xb0.x; lsum = fmaf(e, e, lsum);
            e = v0.w - xb0.y; lsum = fmaf(e, e, lsum);
            e = v1.x - xa1.x; lsum = fmaf(e, e, lsum);
            e = v1.y - xa1.y; lsum = fmaf(e, e, lsum);
            e = v1.z - xb1.x; lsum = fmaf(e, e, lsum);
            e = v1.w - xb1.y; lsum = fmaf(e, e, lsum);
            e = v2.x - xa2.x; lsum = fmaf(e, e, lsum);
            e = v2.y - xa2.y; lsum = fmaf(e, e, lsum);
            e = v2.z - xb2.x; lsum = fmaf(e, e, lsum);
            e = v2.w - xb2.y; lsum = fmaf(e, e, lsum);
        }

        long long p = (long long)ST_ELEMS + (long long)b0 * HWn + hw;
        if (p < out_size)            out[p]            = (float)bj0;
        if (p + HWn < out_size)      out[p + HWn]      = (float)bj1;
        if (p + 2 * HWn < out_size)  out[p + 2 * HWn]  = (float)bj2;
    }

    // ---------------- Pass B: row (b0+3) ----------------
    {
        const float* rp = base + (size_t)(b0 + 3) * Cn * HWn;

        ull x[32];
        #pragma unroll
        for (int i = 0; i < 32; i++)
            x[i] = pack2(rp[(size_t)(2 * i) * HWn], rp[(size_t)(2 * i + 1) * HWn]);

        ull n0 = 0, n1 = 0;
        #pragma unroll
        for (int i = 0; i < 16; i++) {
            fma2(n0, x[2 * i],     x[2 * i]);
            fma2(n1, x[2 * i + 1], x[2 * i + 1]);
        }
        float2 t0 = unpack2(n0), t1 = unpack2(n1);
        const float xx = (t0.x + t0.y) + (t1.x + t1.y);

        float best = FLT_MAX;
        int bj = 0;

        #pragma unroll 2
        for (int j = 0; j < CBn; j++) {
            const ull* __restrict__ crow = (const ull*)(scb + j * Cn);
            ull a0 = 0, a1 = 0;
            #pragma unroll
            for (int i = 0; i < 16; i++) {
                fma2(a0, x[2 * i],     crow[2 * i]);
                fma2(a1, x[2 * i + 1], crow[2 * i + 1]);
            }
            float2 pa = unpack2(a0), pb = unpack2(a1);
            float dot = (pa.x + pa.y) + (pb.x + pb.y);
            float d = (xx - 2.0f * dot) + scn[j];
            if (d < best) { best = d; bj = j; }
        }

        float* st = out + (size_t)(b0 + 3) * Cn * HWn + hw;
        const float4* cr = (const float4*)(cb + bj * Cn);
        #pragma unroll
        for (int i = 0; i < 16; i++) {
            float4 v = cr[i];
            float2 xa = unpack2(x[2 * i]), xb = unpack2(x[2 * i + 1]);
            st[(size_t)(4 * i + 0) * HWn] = v.x;
            st[(size_t)(4 * i + 1) * HWn] = v.y;
            st[(size_t)(4 * i + 2) * HWn] = v.z;
            st[(size_t)(4 * i + 3) * HWn] = v.w;
            float e;
            e = v.x - xa.x; lsum = fmaf(e, e, lsum);
            e = v.y - xa.y; lsum = fmaf(e, e, lsum);
            e = v.z - xb.x; lsum = fmaf(e, e, lsum);
            e = v.w - xb.y; lsum = fmaf(e, e, lsum);
        }

        long long p = (long long)ST_ELEMS + (long long)(b0 + 3) * HWn + hw;
        if (p < out_size) out[p] = (float)bj;
    }

    // Deterministic reduction of loss partials.
    #pragma unroll
    for (int off = 16; off > 0; off >>= 1)
        lsum += __shfl_down_sync(0xffffffffu, lsum, off);
    __shared__ float wsum[NWARPS];
    if (lane == 0) wsum[wid] = lsum;
    __syncthreads();

    __shared__ bool s_last;
    if (tid == 0) {
        float s = 0.f;
        #pragma unroll
        for (int ww = 0; ww < NWARPS; ww++) s += wsum[ww];
        g_blocksums[blockIdx.x] = s;
        __threadfence();
        unsigned int prev = atomicAdd(&g_done_ctr, 1u);
        s_last = (prev == GRID - 1);
    }
    __syncthreads();

    // Last block: deterministic double sum, loss = (1+BETA)*MSE.
    if (s_last && tid == 0) {
        __threadfence();
        double s = 0.0;
        for (int i = 0; i < GRID; i++) s += (double)g_blocksums[i];
        double mse = s / (double)ST_ELEMS;
        long long off = (long long)ST_ELEMS + IDX_ELEMS;
        if (off < out_size) out[off] = (float)(1.25 * mse);
        g_done_ctr = 0;   // reset for next graph replay
    }
}

extern "C" void kernel_launch(void* const* d_in, const int* in_sizes, int n_in,
                              void* d_out, int out_size) {
    const float* inp = (const float*)d_in[0];
    const float* cb  = (const float*)d_in[1];
    // Defensive: swap if metadata order differs.
    if (n_in >= 2 && in_sizes[0] == CBn * Cn && in_sizes[1] == ST_ELEMS) {
        const float* t = inp; inp = cb; cb = t;
    }

    cudaFuncSetAttribute(vq_kernel,
                         cudaFuncAttributeMaxDynamicSharedMemorySize, SMEMSZ);

    vq_kernel<<<GRID, NTHREADS, SMEMSZ>>>(inp, cb, (float*)d_out,
                                          (long long)out_size);
}

// round 11
// speedup vs baseline: 1.0595x; 1.0595x over previous
#include <cuda_runtime.h>
#include <float.h>

// Problem constants: B=32, C=64, H=W=64, code_size=512, BETA=0.25
#define Bn   32
#define Cn   64
#define HWn  4096
#define CBn  512
#define ST_ELEMS  (Bn * Cn * HWn)   // 8388608
#define IDX_ELEMS (Bn * HWn)        // 131072
#define GRID      128               // 1024 warps: 4096 tiles / 1024 = exactly 4 each
#define NTHREADS  256
#define NWARPS    8
// smem: codebook 512*64 floats + cnorm 512 floats
#define SMEMSZ (CBn * Cn * 4 + CBn * 4)

typedef unsigned long long ull;

__device__ float g_blocksums[GRID];
__device__ unsigned int g_done_ctr = 0;

static __device__ __forceinline__ void fma2(ull &acc, ull a, ull b) {
    asm("fma.rn.f32x2 %0, %1, %2, %0;" : "+l"(acc) : "l"(a), "l"(b));
}
static __device__ __forceinline__ ull pack2(float lo, float hi) {
    ull r; asm("mov.b64 %0, {%1, %2};" : "=l"(r) : "f"(lo), "f"(hi)); return r;
}
static __device__ __forceinline__ float2 unpack2(ull v) {
    float2 r; asm("mov.b64 {%0, %1}, %2;" : "=f"(r.x), "=f"(r.y) : "l"(v)); return r;
}

// Persistent kernel: grid=128, 256 threads (8 warps). Global warp id
// w = bid*8 + wid owns row-tiles 4w..4w+3: same 32-wide hw block
// (hwbase = (w>>3)*32), batches b = (4w&31)..(4w&31)+3.
// Pass A: 3 rows/thread (b0,b1,b2) — 6 FMA chains, LDS amortized 3x.
// Pass B: 1 row/thread (b3).
// Row n = hw*B + b of the (N, C) matrix = inputs[b, :, hw].
__global__ void __launch_bounds__(NTHREADS, 1) vq_kernel(
    const float* __restrict__ inp,   // (B, C, H, W)
    const float* __restrict__ cb,    // (512, 64)
    float* __restrict__ out,
    long long out_size)
{
    extern __shared__ float smem[];
    float* scb = smem;              // codebook, row-major 512x64
    float* scn = smem + CBn * Cn;   // per-code squared norms

    const int tid  = threadIdx.x;
    const int wid  = tid >> 5;
    const int lane = tid & 31;

    // Cooperative codebook load into smem (float4).
    for (int i = tid; i < CBn * Cn / 4; i += NTHREADS)
        ((float4*)scb)[i] = ((const float4*)cb)[i];

    // Per-code squared norms (4-lane accumulate + pairwise combine) —
    // identical arithmetic to the passing kernels.
    for (int j = tid; j < CBn; j += NTHREADS) {
        const float4* r = (const float4*)(cb + j * Cn);
        float sa = 0.f, sb = 0.f, sc = 0.f, sd = 0.f;
        #pragma unroll
        for (int i = 0; i < 16; i++) {
            float4 v = r[i];
            sa = fmaf(v.x, v.x, sa);
            sb = fmaf(v.y, v.y, sb);
            sc = fmaf(v.z, v.z, sc);
            sd = fmaf(v.w, v.w, sd);
        }
        scn[j] = (sa + sb) + (sc + sd);
    }
    __syncthreads();

    float lsum = 0.f;

    const int w      = blockIdx.x * NWARPS + wid;   // 0..1023
    const int b0     = (4 * w) & 31;
    const int hw     = ((w >> 3) << 5) + lane;
    const float* __restrict__ base = inp + hw;

    // ---------------- Pass A: rows (b0, b0+1, b0+2) ----------------
    {
        const float* rp0 = base + (size_t)(b0 + 0) * Cn * HWn;
        const float* rp1 = base + (size_t)(b0 + 1) * Cn * HWn;
        const float* rp2 = base + (size_t)(b0 + 2) * Cn * HWn;

        ull x0[32], x1[32], x2[32];
        #pragma unroll
        for (int i = 0; i < 32; i++) {
            x0[i] = pack2(rp0[(size_t)(2 * i) * HWn], rp0[(size_t)(2 * i + 1) * HWn]);
            x1[i] = pack2(rp1[(size_t)(2 * i) * HWn], rp1[(size_t)(2 * i + 1) * HWn]);
            x2[i] = pack2(rp2[(size_t)(2 * i) * HWn], rp2[(size_t)(2 * i + 1) * HWn]);
        }

        // Row squared norms — same accumulator split as the passing kernels.
        ull n0a = 0, n0b = 0, n1a = 0, n1b = 0, n2a = 0, n2b = 0;
        #pragma unroll
        for (int i = 0; i < 16; i++) {
            fma2(n0a, x0[2 * i],     x0[2 * i]);
            fma2(n0b, x0[2 * i + 1], x0[2 * i + 1]);
            fma2(n1a, x1[2 * i],     x1[2 * i]);
            fma2(n1b, x1[2 * i + 1], x1[2 * i + 1]);
            fma2(n2a, x2[2 * i],     x2[2 * i]);
            fma2(n2b, x2[2 * i + 1], x2[2 * i + 1]);
        }
        float2 t0 = unpack2(n0a), t1 = unpack2(n0b);
        const float xx0 = (t0.x + t0.y) + (t1.x + t1.y);
        float2 t2 = unpack2(n1a), t3 = unpack2(n1b);
        const float xx1 = (t2.x + t2.y) + (t3.x + t3.y);
        float2 t4 = unpack2(n2a), t5 = unpack2(n2b);
        const float xx2 = (t4.x + t4.y) + (t5.x + t5.y);

        float best0 = FLT_MAX, best1 = FLT_MAX, best2 = FLT_MAX;
        int bj0 = 0, bj1 = 0, bj2 = 0;

        #pragma unroll 1
        for (int j = 0; j < CBn; j++) {
            const ull* __restrict__ crow = (const ull*)(scb + j * Cn);
            ull a0 = 0, a1 = 0, c0 = 0, c1 = 0, e0 = 0, e1 = 0;
            #pragma unroll
            for (int i = 0; i < 16; i++) {
                ull ccx = crow[2 * i];
                ull ccy = crow[2 * i + 1];
                fma2(a0, x0[2 * i],     ccx);
                fma2(a1, x0[2 * i + 1], ccy);
                fma2(c0, x1[2 * i],     ccx);
                fma2(c1, x1[2 * i + 1], ccy);
                fma2(e0, x2[2 * i],     ccx);
                fma2(e1, x2[2 * i + 1], ccy);
            }
            float2 pa = unpack2(a0), pb = unpack2(a1);
            float dot0 = (pa.x + pa.y) + (pb.x + pb.y);
            float2 qa = unpack2(c0), qb = unpack2(c1);
            float dot1 = (qa.x + qa.y) + (qb.x + qb.y);
            float2 ra = unpack2(e0), rb = unpack2(e1);
            float dot2 = (ra.x + ra.y) + (rb.x + rb.y);

            float cn = scn[j];
            float d0 = (xx0 - 2.0f * dot0) + cn;
            float d1 = (xx1 - 2.0f * dot1) + cn;
            float d2 = (xx2 - 2.0f * dot2) + cn;
            if (d0 < best0) { best0 = d0; bj0 = j; }
            if (d1 < best1) { best1 = d1; bj1 = j; }
            if (d2 < best2) { best2 = d2; bj2 = j; }
        }

        // Epilogue: gather, write st + indices, loss partials.
        float* st0 = out + (size_t)(b0 + 0) * Cn * HWn + hw;
        float* st1 = out + (size_t)(b0 + 1) * Cn * HWn + hw;
        float* st2 = out + (size_t)(b0 + 2) * Cn * HWn + hw;
        const float4* c0r = (const float4*)(cb + bj0 * Cn);
        const float4* c1r = (const float4*)(cb + bj1 * Cn);
        const float4* c2r = (const float4*)(cb + bj2 * Cn);
        #pragma unroll
        for (int i = 0; i < 16; i++) {
            float4 v0 = c0r[i], v1 = c1r[i], v2 = c2r[i];
            float2 xa0 = unpack2(x0[2 * i]), xb0 = unpack2(x0[2 * i + 1]);
            float2 xa1 = unpack2(x1[2 * i]), xb1 = unpack2(x1[2 * i + 1]);
            float2 xa2 = unpack2(x2[2 * i]), xb2 = unpack2(x2[2 * i + 1]);

            st0[(size_t)(4 * i + 0) * HWn] = v0.x;
            st0[(size_t)(4 * i + 1) * HWn] = v0.y;
            st0[(size_t)(4 * i + 2) * HWn] = v0.z;
            st0[(size_t)(4 * i + 3) * HWn] = v0.w;
            st1[(size_t)(4 * i + 0) * HWn] = v1.x;
            st1[(size_t)(4 * i + 1) * HWn] = v1.y;
            st1[(size_t)(4 * i + 2) * HWn] = v1.z;
            st1[(size_t)(4 * i + 3) * HWn] = v1.w;
            st2[(size_t)(4 * i + 0) * HWn] = v2.x;
            st2[(size_t)(4 * i + 1) * HWn] = v2.y;
            st2[(size_t)(4 * i + 2) * HWn] = v2.z;
            st2[(size_t)(4 * i + 3) * HWn] = v2.w;

            float e;
            e = v0.x - xa0.x; lsum = fmaf(e, e, lsum);
            e = v0.y - xa0.y; lsum = fmaf(e, e, lsum);
            e = v0.z - xb0.x; lsum = fmaf(e, e, lsum);
            e = v0.w - xb0.y; lsum = fmaf(e, e, lsum);
            e = v1.x - xa1.x; lsum = fmaf(e, e, lsum);
            e = v1.y - xa1.y; lsum = fmaf(e, e, lsum);
            e = v1.z - xb1.x; lsum = fmaf(e, e, lsum);
            e = v1.w - xb1.y; lsum = fmaf(e, e, lsum);
            e = v2.x - xa2.x; lsum = fmaf(e, e, lsum);
            e = v2.y - xa2.y; lsum = fmaf(e, e, lsum);
            e = v2.z - xb2.x; lsum = fmaf(e, e, lsum);
            e = v2.w - xb2.y; lsum = fmaf(e, e, lsum);
        }

        long long p = (long long)ST_ELEMS + (long long)b0 * HWn + hw;
        if (p < out_size)            out[p]            = (float)bj0;
        if (p + HWn < out_size)      out[p + HWn]      = (float)bj1;
        if (p + 2 * HWn < out_size)  out[p + 2 * HWn]  = (float)bj2;
    }

    // ---------------- Pass B: row (b0+3) ----------------
    {
        const float* rp = base + (size_t)(b0 + 3) * Cn * HWn;

        ull x[32];
        #pragma unroll
        for (int i = 0; i < 32; i++)
            x[i] = pack2(rp[(size_t)(2 * i) * HWn], rp[(size_t)(2 * i + 1) * HWn]);

        ull n0 = 0, n1 = 0;
        #pragma unroll
        for (int i = 0; i < 16; i++) {
            fma2(n0, x[2 * i],     x[2 * i]);
            fma2(n1, x[2 * i + 1], x[2 * i + 1]);
        }
        float2 t0 = unpack2(n0), t1 = unpack2(n1);
        const float xx = (t0.x + t0.y) + (t1.x + t1.y);

        float best = FLT_MAX;
        int bj = 0;

        #pragma unroll 2
        for (int j = 0; j < CBn; j++) {
            const ull* __restrict__ crow = (const ull*)(scb + j * Cn);
            ull a0 = 0, a1 = 0;
            #pragma unroll
            for (int i = 0; i < 16; i++) {
                fma2(a0, x[2 * i],     crow[2 * i]);
                fma2(a1, x[2 * i + 1], crow[2 * i + 1]);
            }
            float2 pa = unpack2(a0), pb = unpack2(a1);
            float dot = (pa.x + pa.y) + (pb.x + pb.y);
            float d = (xx - 2.0f * dot) + scn[j];
            if (d < best) { best = d; bj = j; }
        }

        float* st = out + (size_t)(b0 + 3) * Cn * HWn + hw;
        const float4* cr = (const float4*)(cb + bj * Cn);
        #pragma unroll
        for (int i = 0; i < 16; i++) {
            float4 v = cr[i];
            float2 xa = unpack2(x[2 * i]), xb = unpack2(x[2 * i + 1]);
            st[(size_t)(4 * i + 0) * HWn] = v.x;
            st[(size_t)(4 * i + 1) * HWn] = v.y;
            st[(size_t)(4 * i + 2) * HWn] = v.z;
            st[(size_t)(4 * i + 3) * HWn] = v.w;
            float e;
            e = v.x - xa.x; lsum = fmaf(e, e, lsum);
            e = v.y - xa.y; lsum = fmaf(e, e, lsum);
            e = v.z - xb.x; lsum = fmaf(e, e, lsum);
            e = v.w - xb.y; lsum = fmaf(e, e, lsum);
        }

        long long p = (long long)ST_ELEMS + (long long)(b0 + 3) * HWn + hw;
        if (p < out_size) out[p] = (float)bj;
    }

    // Deterministic reduction of loss partials.
    #pragma unroll
    for (int off = 16; off > 0; off >>= 1)
        lsum += __shfl_down_sync(0xffffffffu, lsum, off);
    __shared__ float wsum[NWARPS];
    if (lane == 0) wsum[wid] = lsum;
    __syncthreads();

    __shared__ bool s_last;
    if (tid == 0) {
        float s = 0.f;
        #pragma unroll
        for (int ww = 0; ww < NWARPS; ww++) s += wsum[ww];
        g_blocksums[blockIdx.x] = s;
        __threadfence();
        unsigned int prev = atomicAdd(&g_done_ctr, 1u);
        s_last = (prev == GRID - 1);
    }
    __syncthreads();

    // Last block: deterministic double sum, loss = (1+BETA)*MSE.
    if (s_last && tid == 0) {
        __threadfence();
        double s = 0.0;
        for (int i = 0; i < GRID; i++) s += (double)g_blocksums[i];
        double mse = s / (double)ST_ELEMS;
        long long off = (long long)ST_ELEMS + IDX_ELEMS;
        if (off < out_size) out[off] = (float)(1.25 * mse);
        g_done_ctr = 0;   // reset for next graph replay
    }
}

extern "C" void kernel_launch(void* const* d_in, const int* in_sizes, int n_in,
                              void* d_out, int out_size) {
    const float* inp = (const float*)d_in[0];
    const float* cb  = (const float*)d_in[1];
    // Defensive: swap if metadata order differs.
    if (n_in >= 2 && in_sizes[0] == CBn * Cn && in_sizes[1] == ST_ELEMS) {
        const float* t = inp; inp = cb; cb = t;
    }

    cudaFuncSetAttribute(vq_kernel,
                         cudaFuncAttributeMaxDynamicSharedMemorySize, SMEMSZ);

    vq_kernel<<<GRID, NTHREADS, SMEMSZ>>>(inp, cb, (float*)d_out,
                                          (long long)out_size);
}

// round 12
// speedup vs baseline: 1.0600x; 1.0005x over previous
#include <cuda_runtime.h>
#include <float.h>

// Problem constants: B=32, C=64, H=W=64, code_size=512, BETA=0.25
#define Bn   32
#define Cn   64
#define HWn  4096
#define CBn  512
#define ST_ELEMS  (Bn * Cn * HWn)   // 8388608
#define IDX_ELEMS (Bn * HWn)        // 131072
#define GRID      128               // 1024 warps: 4096 tiles / 1024 = exactly 4 each
#define NTHREADS  256
#define NWARPS    8
// smem: codebook 512*64 floats + cnorm 512 floats
#define SMEMSZ (CBn * Cn * 4 + CBn * 4)

typedef unsigned long long ull;

__device__ float g_blocksums[GRID];
__device__ unsigned int g_done_ctr = 0;

static __device__ __forceinline__ void fma2(ull &acc, ull a, ull b) {
    asm("fma.rn.f32x2 %0, %1, %2, %0;" : "+l"(acc) : "l"(a), "l"(b));
}
static __device__ __forceinline__ ull pack2(float lo, float hi) {
    ull r; asm("mov.b64 %0, {%1, %2};" : "=l"(r) : "f"(lo), "f"(hi)); return r;
}
static __device__ __forceinline__ float2 unpack2(ull v) {
    float2 r; asm("mov.b64 {%0, %1}, %2;" : "=f"(r.x), "=f"(r.y) : "l"(v)); return r;
}

// Persistent kernel: grid=128, 256 threads (8 warps). Global warp id
// w = bid*8 + wid owns row-tiles 4w..4w+3: same 32-wide hw block
// (hwbase = (w>>3)*32), batches b = (4w&31)..(4w&31)+3.
// Pass A: 3 rows/thread (b0,b1,b2) — 6 FMA chains, LDS amortized 3x.
// Pass B: 1 row/thread (b3).
// Row n = hw*B + b of the (N, C) matrix = inputs[b, :, hw].
__global__ void __launch_bounds__(NTHREADS, 1) vq_kernel(
    const float* __restrict__ inp,   // (B, C, H, W)
    const float* __restrict__ cb,    // (512, 64)
    float* __restrict__ out,
    long long out_size)
{
    extern __shared__ float smem[];
    float* scb = smem;              // codebook, row-major 512x64
    float* scn = smem + CBn * Cn;   // per-code squared norms

    const int tid  = threadIdx.x;
    const int wid  = tid >> 5;
    const int lane = tid & 31;

    // Cooperative codebook load into smem (float4).
    for (int i = tid; i < CBn * Cn / 4; i += NTHREADS)
        ((float4*)scb)[i] = ((const float4*)cb)[i];

    // Per-code squared norms (4-lane accumulate + pairwise combine) —
    // identical arithmetic to the passing kernels.
    for (int j = tid; j < CBn; j += NTHREADS) {
        const float4* r = (const float4*)(cb + j * Cn);
        float sa = 0.f, sb = 0.f, sc = 0.f, sd = 0.f;
        #pragma unroll
        for (int i = 0; i < 16; i++) {
            float4 v = r[i];
            sa = fmaf(v.x, v.x, sa);
            sb = fmaf(v.y, v.y, sb);
            sc = fmaf(v.z, v.z, sc);
            sd = fmaf(v.w, v.w, sd);
        }
        scn[j] = (sa + sb) + (sc + sd);
    }
    __syncthreads();

    float lsum = 0.f;

    const int w      = blockIdx.x * NWARPS + wid;   // 0..1023
    const int b0     = (4 * w) & 31;
    const int hw     = ((w >> 3) << 5) + lane;
    const float* __restrict__ base = inp + hw;

    // ---------------- Pass A: rows (b0, b0+1, b0+2) ----------------
    {
        const float* rp0 = base + (size_t)(b0 + 0) * Cn * HWn;
        const float* rp1 = base + (size_t)(b0 + 1) * Cn * HWn;
        const float* rp2 = base + (size_t)(b0 + 2) * Cn * HWn;

        ull x0[32], x1[32], x2[32];
        #pragma unroll
        for (int i = 0; i < 32; i++) {
            x0[i] = pack2(rp0[(size_t)(2 * i) * HWn], rp0[(size_t)(2 * i + 1) * HWn]);
            x1[i] = pack2(rp1[(size_t)(2 * i) * HWn], rp1[(size_t)(2 * i + 1) * HWn]);
            x2[i] = pack2(rp2[(size_t)(2 * i) * HWn], rp2[(size_t)(2 * i + 1) * HWn]);
        }

        // Row squared norms — same accumulator split as the passing kernels.
        ull n0a = 0, n0b = 0, n1a = 0, n1b = 0, n2a = 0, n2b = 0;
        #pragma unroll
        for (int i = 0; i < 16; i++) {
            fma2(n0a, x0[2 * i],     x0[2 * i]);
            fma2(n0b, x0[2 * i + 1], x0[2 * i + 1]);
            fma2(n1a, x1[2 * i],     x1[2 * i]);
            fma2(n1b, x1[2 * i + 1], x1[2 * i + 1]);
            fma2(n2a, x2[2 * i],     x2[2 * i]);
            fma2(n2b, x2[2 * i + 1], x2[2 * i + 1]);
        }
        float2 t0 = unpack2(n0a), t1 = unpack2(n0b);
        const float xx0 = (t0.x + t0.y) + (t1.x + t1.y);
        float2 t2 = unpack2(n1a), t3 = unpack2(n1b);
        const float xx1 = (t2.x + t2.y) + (t3.x + t3.y);
        float2 t4 = unpack2(n2a), t5 = unpack2(n2b);
        const float xx2 = (t4.x + t4.y) + (t5.x + t5.y);

        float best0 = FLT_MAX, best1 = FLT_MAX, best2 = FLT_MAX;
        int bj0 = 0, bj1 = 0, bj2 = 0;

        #pragma unroll 1
        for (int j = 0; j < CBn; j++) {
            const ull* __restrict__ crow = (const ull*)(scb + j * Cn);
            ull a0 = 0, a1 = 0, c0 = 0, c1 = 0, e0 = 0, e1 = 0;
            #pragma unroll
            for (int i = 0; i < 16; i++) {
                ull ccx = crow[2 * i];
                ull ccy = crow[2 * i + 1];
                fma2(a0, x0[2 * i],     ccx);
                fma2(a1, x0[2 * i + 1], ccy);
                fma2(c0, x1[2 * i],     ccx);
                fma2(c1, x1[2 * i + 1], ccy);
                fma2(e0, x2[2 * i],     ccx);
                fma2(e1, x2[2 * i + 1], ccy);
            }
            float2 pa = unpack2(a0), pb = unpack2(a1);
            float dot0 = (pa.x + pa.y) + (pb.x + pb.y);
            float2 qa = unpack2(c0), qb = unpack2(c1);
            float dot1 = (qa.x + qa.y) + (qb.x + qb.y);
            float2 ra = unpack2(e0), rb = unpack2(e1);
            float dot2 = (ra.x + ra.y) + (rb.x + rb.y);

            float cn = scn[j];
            float d0 = (xx0 - 2.0f * dot0) + cn;
            float d1 = (xx1 - 2.0f * dot1) + cn;
            float d2 = (xx2 - 2.0f * dot2) + cn;
            if (d0 < best0) { best0 = d0; bj0 = j; }
            if (d1 < best1) { best1 = d1; bj1 = j; }
            if (d2 < best2) { best2 = d2; bj2 = j; }
        }

        // Epilogue: gather, write st + indices, loss partials.
        float* st0 = out + (size_t)(b0 + 0) * Cn * HWn + hw;
        float* st1 = out + (size_t)(b0 + 1) * Cn * HWn + hw;
        float* st2 = out + (size_t)(b0 + 2) * Cn * HWn + hw;
        const float4* c0r = (const float4*)(cb + bj0 * Cn);
        const float4* c1r = (const float4*)(cb + bj1 * Cn);
        const float4* c2r = (const float4*)(cb + bj2 * Cn);
        #pragma unroll
        for (int i = 0; i < 16; i++) {
            float4 v0 = c0r[i], v1 = c1r[i], v2 = c2r[i];
            float2 xa0 = unpack2(x0[2 * i]), xb0 = unpack2(x0[2 * i + 1]);
            float2 xa1 = unpack2(x1[2 * i]), xb1 = unpack2(x1[2 * i + 1]);
            float2 xa2 = unpack2(x2[2 * i]), xb2 = unpack2(x2[2 * i + 1]);

            st0[(size_t)(4 * i + 0) * HWn] = v0.x;
            st0[(size_t)(4 * i + 1) * HWn] = v0.y;
            st0[(size_t)(4 * i + 2) * HWn] = v0.z;
            st0[(size_t)(4 * i + 3) * HWn] = v0.w;
            st1[(size_t)(4 * i + 0) * HWn] = v1.x;
            st1[(size_t)(4 * i + 1) * HWn] = v1.y;
            st1[(size_t)(4 * i + 2) * HWn] = v1.z;
            st1[(size_t)(4 * i + 3) * HWn] = v1.w;
            st2[(size_t)(4 * i + 0) * HWn] = v2.x;
            st2[(size_t)(4 * i + 1) * HWn] = v2.y;
            st2[(size_t)(4 * i + 2) * HWn] = v2.z;
            st2[(size_t)(4 * i + 3) * HWn] = v2.w;

            float e;
            e = v0.x - xa0.x; lsum = fmaf(e, e, lsum);
            e = v0.y - xa0.y; lsum = fmaf(e, e, lsum);
            e = v0.z - xb0.x; lsum = fmaf(e, e, lsum);
            e = v0.w - xb0.y; lsum = fmaf(e, e, lsum);
            e = v1.x - xa1.x; lsum = fmaf(e, e, lsum);
            e = v1.y - xa1.y; lsum = fmaf(e, e, lsum);
            e = v1.z - xb1.x; lsum = fmaf(e, e, lsum);
            e = v1.w - xb1.y; lsum = fmaf(e, e, lsum);
            e = v2.x - xa2.x; lsum = fmaf(e, e, lsum);
            e = v2.y - xa2.y; lsum = fmaf(e, e, lsum);
            e = v2.z - xb2.x; lsum = fmaf(e, e, lsum);
            e = v2.w - xb2.y; lsum = fmaf(e, e, lsum);
        }

        long long p = (long long)ST_ELEMS + (long long)b0 * HWn + hw;
        if (p < out_size)            out[p]            = (float)bj0;
        if (p + HWn < out_size)      out[p + HWn]      = (float)bj1;
        if (p + 2 * HWn < out_size)  out[p + 2 * HWn]  = (float)bj2;
    }

    // ---------------- Pass B: row (b0+3) ----------------
    {
        const float* rp = base + (size_t)(b0 + 3) * Cn * HWn;

        ull x[32];
        #pragma unroll
        for (int i = 0; i < 32; i++)
            x[i] = pack2(rp[(size_t)(2 * i) * HWn], rp[(size_t)(2 * i + 1) * HWn]);

        ull n0 = 0, n1 = 0;
        #pragma unroll
        for (int i = 0; i < 16; i++) {
            fma2(n0, x[2 * i],     x[2 * i]);
            fma2(n1, x[2 * i + 1], x[2 * i + 1]);
        }
        float2 t0 = unpack2(n0), t1 = unpack2(n1);
        const float xx = (t0.x + t0.y) + (t1.x + t1.y);

        float best = FLT_MAX;
        int bj = 0;

        #pragma unroll 2
        for (int j = 0; j < CBn; j++) {
            const ull* __restrict__ crow = (const ull*)(scb + j * Cn);
            ull a0 = 0, a1 = 0;
            #pragma unroll
            for (int i = 0; i < 16; i++) {
                fma2(a0, x[2 * i],     crow[2 * i]);
                fma2(a1, x[2 * i + 1], crow[2 * i + 1]);
            }
            float2 pa = unpack2(a0), pb = unpack2(a1);
            float dot = (pa.x + pa.y) + (pb.x + pb.y);
            float d = (xx - 2.0f * dot) + scn[j];
            if (d < best) { best = d; bj = j; }
        }

        float* st = out + (size_t)(b0 + 3) * Cn * HWn + hw;
        const float4* cr = (const float4*)(cb + bj * Cn);
        #pragma unroll
        for (int i = 0; i < 16; i++) {
            float4 v = cr[i];
            float2 xa = unpack2(x[2 * i]), xb = unpack2(x[2 * i + 1]);
            st[(size_t)(4 * i + 0) * HWn] = v.x;
            st[(size_t)(4 * i + 1) * HWn] = v.y;
            st[(size_t)(4 * i + 2) * HWn] = v.z;
            st[(size_t)(4 * i + 3) * HWn] = v.w;
            float e;
            e = v.x - xa.x; lsum = fmaf(e, e, lsum);
            e = v.y - xa.y; lsum = fmaf(e, e, lsum);
            e = v.z - xb.x; lsum = fmaf(e, e, lsum);
            e = v.w - xb.y; lsum = fmaf(e, e, lsum);
        }

        long long p = (long long)ST_ELEMS + (long long)(b0 + 3) * HWn + hw;
        if (p < out_size) out[p] = (float)bj;
    }

    // Deterministic reduction of loss partials.
    #pragma unroll
    for (int off = 16; off > 0; off >>= 1)
        lsum += __shfl_down_sync(0xffffffffu, lsum, off);
    __shared__ float wsum[NWARPS];
    if (lane == 0) wsum[wid] = lsum;
    __syncthreads();

    __shared__ bool s_last;
    if (tid == 0) {
        float s = 0.f;
        #pragma unroll
        for (int ww = 0; ww < NWARPS; ww++) s += wsum[ww];
        g_blocksums[blockIdx.x] = s;
        __threadfence();
        unsigned int prev = atomicAdd(&g_done_ctr, 1u);
        s_last = (prev == GRID - 1);
    }
    __syncthreads();

    // Last block: deterministic double sum, loss = (1+BETA)*MSE.
    if (s_last && tid == 0) {
        __threadfence();
        double s = 0.0;
        for (int i = 0; i < GRID; i++) s += (double)g_blocksums[i];
        double mse = s / (double)ST_ELEMS;
        long long off = (long long)ST_ELEMS + IDX_ELEMS;
        if (off < out_size) out[off] = (float)(1.25 * mse);
        g_done_ctr = 0;   // reset for next graph replay
    }
}

extern "C" void kernel_launch(void* const* d_in, const int* in_sizes, int n_in,
                              void* d_out, int out_size) {
    const float* inp = (const float*)d_in[0];
    const float* cb  = (const float*)d_in[1];
    // Defensive: swap if metadata order differs.
    if (n_in >= 2 && in_sizes[0] == CBn * Cn && in_sizes[1] == ST_ELEMS) {
        const float* t = inp; inp = cb; cb = t;
    }

    cudaFuncSetAttribute(vq_kernel,
                         cudaFuncAttributeMaxDynamicSharedMemorySize, SMEMSZ);

    vq_kernel<<<GRID, NTHREADS, SMEMSZ>>>(inp, cb, (float*)d_out,
                                          (long long)out_size);
}